// round 5
// baseline (speedup 1.0000x reference)
#include <cuda_runtime.h>

// LorentzAvgPool2d: x[32,128,128,64] fp32 NHWC -> out[32,64,64,64]
// 2x2/stride-2 avg pool, then Lorentz centroid normalization:
//   inner = -a0^2 + sum_{c>0} a_c^2
//   out   = a * rsqrt(max(|inner|, 1e-8))      (k=1)
//
// R5: persistent grid-stride (one resident wave: 1184 CTAs), 256-bit
//     loads/stores, 8-lane group per output pixel. Default caching.

static constexpr int B = 32;
static constexpr int H = 128;
static constexpr int W = 128;
static constexpr int C = 64;
static constexpr int OH = H / 2;
static constexpr int OW = W / 2;
static constexpr int NPIX = B * OH * OW;          // 131072 output pixels
static constexpr float EPS = 1e-8f;

static constexpr int THREADS = 256;
static constexpr int PIX_PER_BLOCK = THREADS / 8; // 32
static constexpr int NBLOCKS = 1184;              // 148 SMs x 8 CTAs (one wave)

struct F8 { float v0, v1, v2, v3, v4, v5, v6, v7; };

__device__ __forceinline__ F8 ldg256(const float* p) {
    F8 r;
    asm volatile("ld.global.nc.v8.f32 {%0,%1,%2,%3,%4,%5,%6,%7}, [%8];"
                 : "=f"(r.v0), "=f"(r.v1), "=f"(r.v2), "=f"(r.v3),
                   "=f"(r.v4), "=f"(r.v5), "=f"(r.v6), "=f"(r.v7)
                 : "l"(p));
    return r;
}

__device__ __forceinline__ void stg256(float* p, const F8& r) {
    asm volatile("st.global.v8.f32 [%0], {%1,%2,%3,%4,%5,%6,%7,%8};"
                 :: "l"(p),
                    "f"(r.v0), "f"(r.v1), "f"(r.v2), "f"(r.v3),
                    "f"(r.v4), "f"(r.v5), "f"(r.v6), "f"(r.v7)
                 : "memory");
}

__global__ __launch_bounds__(THREADS) void lorentz_avgpool_kernel(
    const float* __restrict__ x, float* __restrict__ out)
{
    const int lane = threadIdx.x & 7;             // 8-channel slice within pixel
    const int co   = lane * 8;                    // channel offset
    const int gidx0 = (blockIdx.x * THREADS + threadIdx.x) >> 3;
    const int gstride = NBLOCKS * PIX_PER_BLOCK;  // pixels per grid pass

    for (int group = gidx0; group < NPIX; group += gstride) {
        const int ow = group & (OW - 1);                    // 0..63
        const int oh = (group >> 6) & (OH - 1);             // 0..63
        const int b  = group >> 12;                         // 0..31

        const int ih = oh * 2;
        const int iw = ow * 2;

        const long base0 = ((long)(b * H + ih) * W + iw) * C;   // row ih
        const long base1 = base0 + (long)W * C;                 // row ih+1

        // 4 independent 256-bit loads (the 2x2 window)
        const F8 a  = ldg256(x + base0 + co);          // (ih,   iw  )
        const F8 bq = ldg256(x + base0 + C + co);      // (ih,   iw+1)
        const F8 c  = ldg256(x + base1 + co);          // (ih+1, iw  )
        const F8 d  = ldg256(x + base1 + C + co);      // (ih+1, iw+1)

        F8 avg;
        avg.v0 = (a.v0 + bq.v0 + c.v0 + d.v0) * 0.25f;
        avg.v1 = (a.v1 + bq.v1 + c.v1 + d.v1) * 0.25f;
        avg.v2 = (a.v2 + bq.v2 + c.v2 + d.v2) * 0.25f;
        avg.v3 = (a.v3 + bq.v3 + c.v3 + d.v3) * 0.25f;
        avg.v4 = (a.v4 + bq.v4 + c.v4 + d.v4) * 0.25f;
        avg.v5 = (a.v5 + bq.v5 + c.v5 + d.v5) * 0.25f;
        avg.v6 = (a.v6 + bq.v6 + c.v6 + d.v6) * 0.25f;
        avg.v7 = (a.v7 + bq.v7 + c.v7 + d.v7) * 0.25f;

        // partial Lorentz inner product; lane 0's channel 0 is time coordinate
        float s = avg.v0 * avg.v0;
        if (lane == 0) s = -s;
        s += avg.v1 * avg.v1 + avg.v2 * avg.v2 + avg.v3 * avg.v3
           + avg.v4 * avg.v4 + avg.v5 * avg.v5 + avg.v6 * avg.v6
           + avg.v7 * avg.v7;

        // reduce across the 8-lane group
        s += __shfl_xor_sync(0xFFFFFFFFu, s, 1);
        s += __shfl_xor_sync(0xFFFFFFFFu, s, 2);
        s += __shfl_xor_sync(0xFFFFFFFFu, s, 4);

        const float inv = rsqrtf(fmaxf(fabsf(s), EPS));

        F8 r;
        r.v0 = avg.v0 * inv; r.v1 = avg.v1 * inv;
        r.v2 = avg.v2 * inv; r.v3 = avg.v3 * inv;
        r.v4 = avg.v4 * inv; r.v5 = avg.v5 * inv;
        r.v6 = avg.v6 * inv; r.v7 = avg.v7 * inv;

        stg256(out + (long)group * C + co, r);
    }
}

extern "C" void kernel_launch(void* const* d_in, const int* in_sizes, int n_in,
                              void* d_out, int out_size)
{
    const float* x = (const float*)d_in[0];
    float* out = (float*)d_out;
    lorentz_avgpool_kernel<<<NBLOCKS, THREADS>>>(x, out);
}

// round 6
// speedup vs baseline: 1.0469x; 1.0469x over previous
#include <cuda_runtime.h>

// LorentzAvgPool2d: x[32,128,128,64] fp32 NHWC -> out[32,64,64,64]
// 2x2/stride-2 avg pool, then Lorentz centroid normalization:
//   inner = -a0^2 + sum_{c>0} a_c^2
//   out   = a * rsqrt(max(|inner|, 1e-8))      (k=1)
//
// R6: one-shot CTAs (persistent loop regressed in R5), 256-bit ld/st,
//     8-lane group handles TWO ow-adjacent output pixels:
//     8 independent LD.256 per thread front-batched, 2 ST.256.

static constexpr int B = 32;
static constexpr int H = 128;
static constexpr int W = 128;
static constexpr int C = 64;
static constexpr int OH = H / 2;
static constexpr int OW = W / 2;
static constexpr int NPIX = B * OH * OW;          // 131072 output pixels
static constexpr int NGRP = NPIX / 2;             // 65536 groups (2 pixels each)
static constexpr float EPS = 1e-8f;

struct F8 { float v0, v1, v2, v3, v4, v5, v6, v7; };

__device__ __forceinline__ F8 ldg256(const float* p) {
    F8 r;
    asm volatile("ld.global.nc.v8.f32 {%0,%1,%2,%3,%4,%5,%6,%7}, [%8];"
                 : "=f"(r.v0), "=f"(r.v1), "=f"(r.v2), "=f"(r.v3),
                   "=f"(r.v4), "=f"(r.v5), "=f"(r.v6), "=f"(r.v7)
                 : "l"(p));
    return r;
}

__device__ __forceinline__ void stg256(float* p, const F8& r) {
    asm volatile("st.global.v8.f32 [%0], {%1,%2,%3,%4,%5,%6,%7,%8};"
                 :: "l"(p),
                    "f"(r.v0), "f"(r.v1), "f"(r.v2), "f"(r.v3),
                    "f"(r.v4), "f"(r.v5), "f"(r.v6), "f"(r.v7)
                 : "memory");
}

__device__ __forceinline__ void acc4(F8& s, const F8& a, const F8& b,
                                     const F8& c, const F8& d) {
    s.v0 = (a.v0 + b.v0 + c.v0 + d.v0) * 0.25f;
    s.v1 = (a.v1 + b.v1 + c.v1 + d.v1) * 0.25f;
    s.v2 = (a.v2 + b.v2 + c.v2 + d.v2) * 0.25f;
    s.v3 = (a.v3 + b.v3 + c.v3 + d.v3) * 0.25f;
    s.v4 = (a.v4 + b.v4 + c.v4 + d.v4) * 0.25f;
    s.v5 = (a.v5 + b.v5 + c.v5 + d.v5) * 0.25f;
    s.v6 = (a.v6 + b.v6 + c.v6 + d.v6) * 0.25f;
    s.v7 = (a.v7 + b.v7 + c.v7 + d.v7) * 0.25f;
}

__global__ __launch_bounds__(256) void lorentz_avgpool_kernel(
    const float* __restrict__ x, float* __restrict__ out)
{
    const int tid   = blockIdx.x * blockDim.x + threadIdx.x;
    const int group = tid >> 3;            // group index (2 output pixels)
    const int lane  = tid & 7;             // 8-channel slice within pixel
    if (group >= NGRP) return;

    // group -> (b, oh, ow2); ow = ow2*2
    const int ow2 = group & (OW / 2 - 1);               // 0..31
    const int oh  = (group >> 5) & (OH - 1);            // 0..63
    const int b   = group >> 11;                        // 0..31

    const int ih = oh * 2;
    const int iw = ow2 * 4;                             // first input column
    const int co = lane * 8;                            // channel offset

    const long base0 = ((long)(b * H + ih) * W + iw) * C;   // row ih
    const long base1 = base0 + (long)W * C;                 // row ih+1

    // 8 independent 256-bit loads, front-batched (2KB contiguous per group)
    const F8 a0 = ldg256(x + base0 + 0 * C + co);
    const F8 a1 = ldg256(x + base0 + 1 * C + co);
    const F8 a2 = ldg256(x + base0 + 2 * C + co);
    const F8 a3 = ldg256(x + base0 + 3 * C + co);
    const F8 b0 = ldg256(x + base1 + 0 * C + co);
    const F8 b1 = ldg256(x + base1 + 1 * C + co);
    const F8 b2 = ldg256(x + base1 + 2 * C + co);
    const F8 b3 = ldg256(x + base1 + 3 * C + co);

    F8 avg0, avg1;
    acc4(avg0, a0, a1, b0, b1);    // window 0: cols iw, iw+1
    acc4(avg1, a2, a3, b2, b3);    // window 1: cols iw+2, iw+3

    // partial Lorentz inner products; lane 0 channel 0 is the time coordinate
    float s0 = avg0.v0 * avg0.v0;
    float s1 = avg1.v0 * avg1.v0;
    if (lane == 0) { s0 = -s0; s1 = -s1; }
    s0 += avg0.v1 * avg0.v1 + avg0.v2 * avg0.v2 + avg0.v3 * avg0.v3
        + avg0.v4 * avg0.v4 + avg0.v5 * avg0.v5 + avg0.v6 * avg0.v6
        + avg0.v7 * avg0.v7;
    s1 += avg1.v1 * avg1.v1 + avg1.v2 * avg1.v2 + avg1.v3 * avg1.v3
        + avg1.v4 * avg1.v4 + avg1.v5 * avg1.v5 + avg1.v6 * avg1.v6
        + avg1.v7 * avg1.v7;

    // reduce across the 8-lane group (both pixels in parallel)
    s0 += __shfl_xor_sync(0xFFFFFFFFu, s0, 1);
    s1 += __shfl_xor_sync(0xFFFFFFFFu, s1, 1);
    s0 += __shfl_xor_sync(0xFFFFFFFFu, s0, 2);
    s1 += __shfl_xor_sync(0xFFFFFFFFu, s1, 2);
    s0 += __shfl_xor_sync(0xFFFFFFFFu, s0, 4);
    s1 += __shfl_xor_sync(0xFFFFFFFFu, s1, 4);

    const float inv0 = rsqrtf(fmaxf(fabsf(s0), EPS));
    const float inv1 = rsqrtf(fmaxf(fabsf(s1), EPS));

    F8 r0, r1;
    r0.v0 = avg0.v0 * inv0; r0.v1 = avg0.v1 * inv0;
    r0.v2 = avg0.v2 * inv0; r0.v3 = avg0.v3 * inv0;
    r0.v4 = avg0.v4 * inv0; r0.v5 = avg0.v5 * inv0;
    r0.v6 = avg0.v6 * inv0; r0.v7 = avg0.v7 * inv0;
    r1.v0 = avg1.v0 * inv1; r1.v1 = avg1.v1 * inv1;
    r1.v2 = avg1.v2 * inv1; r1.v3 = avg1.v3 * inv1;
    r1.v4 = avg1.v4 * inv1; r1.v5 = avg1.v5 * inv1;
    r1.v6 = avg1.v6 * inv1; r1.v7 = avg1.v7 * inv1;

    // output pixels 2*group and 2*group+1 (512B contiguous per group)
    float* op = out + (long)group * 2 * C + co;
    stg256(op, r0);
    stg256(op + C, r1);
}

extern "C" void kernel_launch(void* const* d_in, const int* in_sizes, int n_in,
                              void* d_out, int out_size)
{
    const float* x = (const float*)d_in[0];
    float* out = (float*)d_out;

    const int threads = 256;
    const int grp_per_block = threads / 8;                // 32
    const int blocks = (NGRP + grp_per_block - 1) / grp_per_block;  // 2048
    lorentz_avgpool_kernel<<<blocks, threads>>>(x, out);
}

// round 7
// speedup vs baseline: 1.0690x; 1.0212x over previous
#include <cuda_runtime.h>

// LorentzAvgPool2d: x[32,128,128,64] fp32 NHWC -> out[32,64,64,64]
// 2x2/stride-2 avg pool, then Lorentz centroid normalization:
//   inner = -a0^2 + sum_{c>0} a_c^2
//   out   = a * rsqrt(max(|inner|, 1e-8))      (k=1)
//
// R7: 256-bit ld/st at HIGH occupancy. 16-lane group per output pixel:
//     lane>>3 picks the window column, each lane does 2x LD.256 (rows ih,ih+1)
//     for its column -> only 16 data regs. Column sums combined across the
//     half-groups via shfl_xor(...,8). One ST.256 per lane pair (halves write
//     the same data; only the low half stores).

static constexpr int B = 32;
static constexpr int H = 128;
static constexpr int W = 128;
static constexpr int C = 64;
static constexpr int OH = H / 2;
static constexpr int OW = W / 2;
static constexpr int NPIX = B * OH * OW;          // 131072 output pixels
static constexpr float EPS = 1e-8f;

struct F8 { float v0, v1, v2, v3, v4, v5, v6, v7; };

__device__ __forceinline__ F8 ldg256(const float* p) {
    F8 r;
    asm volatile("ld.global.nc.v8.f32 {%0,%1,%2,%3,%4,%5,%6,%7}, [%8];"
                 : "=f"(r.v0), "=f"(r.v1), "=f"(r.v2), "=f"(r.v3),
                   "=f"(r.v4), "=f"(r.v5), "=f"(r.v6), "=f"(r.v7)
                 : "l"(p));
    return r;
}

__device__ __forceinline__ void stg256(float* p, const F8& r) {
    asm volatile("st.global.v8.f32 [%0], {%1,%2,%3,%4,%5,%6,%7,%8};"
                 :: "l"(p),
                    "f"(r.v0), "f"(r.v1), "f"(r.v2), "f"(r.v3),
                    "f"(r.v4), "f"(r.v5), "f"(r.v6), "f"(r.v7)
                 : "memory");
}

__global__ __launch_bounds__(256) void lorentz_avgpool_kernel(
    const float* __restrict__ x, float* __restrict__ out)
{
    const int tid    = blockIdx.x * blockDim.x + threadIdx.x;
    const int group  = tid >> 4;            // global output pixel index
    const int lane16 = tid & 15;
    const int colsel = lane16 >> 3;         // which window column this lane loads
    const int cs     = (lane16 & 7) * 8;    // channel slice offset
    if (group >= NPIX) return;

    const int ow = group & (OW - 1);                    // 0..63
    const int oh = (group >> 6) & (OH - 1);             // 0..63
    const int b  = group >> 12;                         // 0..31

    const int ih = oh * 2;
    const int iw = ow * 2 + colsel;

    const long base = ((long)(b * H + ih) * W + iw) * C + cs;

    // 2 independent 256-bit loads: rows ih and ih+1, this lane's column
    const F8 t = ldg256(x + base);                  // (ih,   iw+colsel)
    const F8 u = ldg256(x + base + (long)W * C);    // (ih+1, iw+colsel)

    // column sum
    F8 s;
    s.v0 = t.v0 + u.v0; s.v1 = t.v1 + u.v1;
    s.v2 = t.v2 + u.v2; s.v3 = t.v3 + u.v3;
    s.v4 = t.v4 + u.v4; s.v5 = t.v5 + u.v5;
    s.v6 = t.v6 + u.v6; s.v7 = t.v7 + u.v7;

    // combine with the other column's sum (lane ^ 8 has same channel slice)
    F8 avg;
    avg.v0 = (s.v0 + __shfl_xor_sync(0xFFFFFFFFu, s.v0, 8)) * 0.25f;
    avg.v1 = (s.v1 + __shfl_xor_sync(0xFFFFFFFFu, s.v1, 8)) * 0.25f;
    avg.v2 = (s.v2 + __shfl_xor_sync(0xFFFFFFFFu, s.v2, 8)) * 0.25f;
    avg.v3 = (s.v3 + __shfl_xor_sync(0xFFFFFFFFu, s.v3, 8)) * 0.25f;
    avg.v4 = (s.v4 + __shfl_xor_sync(0xFFFFFFFFu, s.v4, 8)) * 0.25f;
    avg.v5 = (s.v5 + __shfl_xor_sync(0xFFFFFFFFu, s.v5, 8)) * 0.25f;
    avg.v6 = (s.v6 + __shfl_xor_sync(0xFFFFFFFFu, s.v6, 8)) * 0.25f;
    avg.v7 = (s.v7 + __shfl_xor_sync(0xFFFFFFFFu, s.v7, 8)) * 0.25f;

    // partial Lorentz inner product; channel 0 (lane16==0 or 8, v0) is the
    // time coordinate
    float p = avg.v0 * avg.v0;
    if ((lane16 & 7) == 0) p = -p;
    p += avg.v1 * avg.v1 + avg.v2 * avg.v2 + avg.v3 * avg.v3
       + avg.v4 * avg.v4 + avg.v5 * avg.v5 + avg.v6 * avg.v6
       + avg.v7 * avg.v7;

    // reduce across the 8 channel slices (both halves hold identical avg)
    p += __shfl_xor_sync(0xFFFFFFFFu, p, 1);
    p += __shfl_xor_sync(0xFFFFFFFFu, p, 2);
    p += __shfl_xor_sync(0xFFFFFFFFu, p, 4);

    const float inv = rsqrtf(fmaxf(fabsf(p), EPS));

    // only the low half of each 16-lane group stores (8 lanes x 32B = 256B)
    if (colsel == 0) {
        F8 r;
        r.v0 = avg.v0 * inv; r.v1 = avg.v1 * inv;
        r.v2 = avg.v2 * inv; r.v3 = avg.v3 * inv;
        r.v4 = avg.v4 * inv; r.v5 = avg.v5 * inv;
        r.v6 = avg.v6 * inv; r.v7 = avg.v7 * inv;
        stg256(out + (long)group * C + cs, r);
    }
}

extern "C" void kernel_launch(void* const* d_in, const int* in_sizes, int n_in,
                              void* d_out, int out_size)
{
    const float* x = (const float*)d_in[0];
    float* out = (float*)d_out;

    const int threads = 256;
    const int pix_per_block = threads / 16;               // 16
    const int blocks = (NPIX + pix_per_block - 1) / pix_per_block;  // 8192
    lorentz_avgpool_kernel<<<blocks, threads>>>(x, out);
}